// round 13
// baseline (speedup 1.0000x reference)
#include <cuda_runtime.h>
#include <cuda_fp16.h>
#include <cstdint>

__device__ float  g_h0[1024 * 128 * 64];
__device__ float  g_h1[1024 * 128 * 64];
__device__ __half g_wt0[9 * 16384];     // L0 folded, chunk-tiled (R11 mapping)
__device__ __half g_wt1[256 * 4096];    // L1/L2: Wt[c][h][kk], kk = 2m+nl, n = 2c+nl
__device__ __half g_wt2[256 * 4096];

__device__ __forceinline__ uint32_t smem_u32(const void* p) {
    uint32_t r;
    asm("{ .reg .u64 t; cvta.to.shared.u64 t, %1; cvt.u32.u64 %0, t; }" : "=r"(r) : "l"(p));
    return r;
}
__device__ __forceinline__ uint32_t h2u(__half2 v) { return *reinterpret_cast<uint32_t*>(&v); }
__device__ __forceinline__ uint32_t hmul2(uint32_t a, uint32_t b) {
    uint32_t r;
    asm("mul.rn.f16x2 %0, %1, %2;" : "=r"(r) : "r"(a), "r"(b));
    return r;
}
__device__ __forceinline__ void cp16(uint32_t dst, const void* src) {
    asm volatile("cp.async.cg.shared.global [%0], [%1], 16;" :: "r"(dst), "l"(src) : "memory");
}
__device__ __forceinline__ void cp_commit() { asm volatile("cp.async.commit_group;" ::: "memory"); }
template <int N>
__device__ __forceinline__ void cp_wait() { asm volatile("cp.async.wait_group %0;" :: "n"(N) : "memory"); }
__device__ __forceinline__ void cp_mbar_arrive(uint32_t mbar) {
    asm volatile("cp.async.mbarrier.arrive.noinc.shared.b64 [%0];" :: "r"(mbar) : "memory");
}
__device__ __forceinline__ void mbar_init(uint32_t a, uint32_t c) {
    asm volatile("mbarrier.init.shared.b64 [%0], %1;" :: "r"(a), "r"(c) : "memory");
}
__device__ __forceinline__ void mbar_arrive(uint32_t a) {
    asm volatile("mbarrier.arrive.shared.b64 _, [%0];" :: "r"(a) : "memory");
}
__device__ __forceinline__ void mbar_wait(uint32_t a, uint32_t ph) {
    asm volatile(
        "{\n\t.reg .pred P;\n"
        "W_%=:\n\tmbarrier.try_wait.parity.shared.b64 P, [%0], %1, 0x989680;\n\t"
        "@P bra.uni D_%=;\n\tbra.uni W_%=;\nD_%=:\n\t}"
        :: "r"(a), "r"(ph) : "memory");
}
__device__ __forceinline__ void ldsm4(uint32_t* r, uint32_t a) {
    asm volatile("ldmatrix.sync.aligned.m8n8.x4.shared.b16 {%0,%1,%2,%3}, [%4];"
                 : "=r"(r[0]), "=r"(r[1]), "=r"(r[2]), "=r"(r[3]) : "r"(a));
}
__device__ __forceinline__ void mma16(float* c, const uint32_t* a, const uint32_t* b) {
    asm volatile("mma.sync.aligned.m16n8k16.row.col.f32.f16.f16.f32 "
                 "{%0,%1,%2,%3},{%4,%5,%6,%7},{%8,%9},{%0,%1,%2,%3};"
                 : "+f"(c[0]), "+f"(c[1]), "+f"(c[2]), "+f"(c[3])
                 : "r"(a[0]), "r"(a[1]), "r"(a[2]), "r"(a[3]), "r"(b[0]), "r"(b[1]));
}
__device__ __forceinline__ int tribase(int m) { return 32 * m - ((m * (m - 1)) >> 1); }

// ---------------- prep: weight transposes + out init ----------------
__global__ void __launch_bounds__(256)
prep(const float* __restrict__ W0, const float* __restrict__ W1, const float* __restrict__ W2,
     const float* __restrict__ fcb, float* __restrict__ out,
     __half* __restrict__ wt0, __half* __restrict__ wt1, __half* __restrict__ wt2) {
    const int bx = blockIdx.x, t = threadIdx.x;
    if (bx >= 137) { out[(bx - 137) * 256 + t] = fcb[0]; return; }
    __shared__ __half s[64 * 256];
    __half* dst;
    if (bx < 9) {
        const int c = bx, p0 = 64 * c;
        int m = 0;
        while (tribase(m + 1) <= p0) ++m;
        int n = m + (p0 - tribase(m));
        for (int kk = 0; kk < 64; kk++) {
            float v = 0.0f;
            if (p0 + kk < 528) {
                v = W0[(size_t)(m * 32 + n) * 256 + t];
                if (n > m) v += W0[(size_t)(n * 32 + m) * 256 + t];
                if (++n == 32) { ++m; n = m; }
            }
            s[kk * 256 + t] = __float2half_rn(v);
        }
        dst = wt0 + (size_t)c * 16384 + (size_t)t * 64;
    } else {
        const int c = (bx < 73) ? (bx - 9) : (bx - 73);
        const float* W = (bx < 73) ? W1 : W2;
#pragma unroll 4
        for (int kk = 0; kk < 64; kk++) {
            const int m = kk >> 1, nl = kk & 1;          // kk = 2m + nl
            const int k = m * 128 + 2 * c + nl;
            s[kk * 256 + t] = __float2half_rn(W[(size_t)k * 256 + t]);
        }
        dst = ((bx < 73) ? wt1 : wt2) + (size_t)c * 16384 + (size_t)t * 64;
    }
    __syncthreads();
#pragma unroll
    for (int j = 0; j < 8; j++) {
        uint4 v;
        v.x = h2u(__halves2half2(s[(8 * j + 0) * 256 + t], s[(8 * j + 1) * 256 + t]));
        v.y = h2u(__halves2half2(s[(8 * j + 2) * 256 + t], s[(8 * j + 3) * 256 + t]));
        v.z = h2u(__halves2half2(s[(8 * j + 4) * 256 + t], s[(8 * j + 5) * 256 + t]));
        v.w = h2u(__halves2half2(s[(8 * j + 6) * 256 + t], s[(8 * j + 7) * 256 + t]));
        *reinterpret_cast<uint4*>(dst + 8 * j) = v;
    }
}

// ---------------- L0: R11 proven warp-specialized folded kernel ----------------
__global__ void __launch_bounds__(192, 2)
cin_l0(const float* __restrict__ x, const float* __restrict__ bias,
       const float* __restrict__ fcW, float* __restrict__ out) {
    constexpr int NC = 9;
    extern __shared__ char smc[];
    const uint32_t sb0 = smem_u32(smc);
    const uint32_t sb  = (sb0 + 1023u) & ~1023u;
    char* const smb    = smc + (sb - sb0);
    const uint32_t stg0 = sb + 1024u;
    const int t = threadIdx.x, lane = t & 31, wid = t >> 5;
    const int b0 = (blockIdx.x >> 1) * 2, hseg = (blockIdx.x & 1) * 128;

    if (t == 0) {
#pragma unroll
        for (int s = 0; s < 3; s++) { mbar_init(sb + 16 * s, 128); mbar_init(sb + 16 * s + 8, 128); }
    }
    __syncthreads();

    if (t >= 128) {
        const int ptid = t - 128;
        float xr0[32], xr1[32];
        {
            const float* xp0 = x + (size_t)b0 * 2048 + ptid;
            const float* xp1 = x + (size_t)(b0 + 1) * 2048 + ptid;
#pragma unroll
            for (int m = 0; m < 32; m++) { xr0[m] = xp0[m * 64]; xr1[m] = xp1[m * 64]; }
        }
        int ps = 0; uint32_t pph = 1;
        for (int c = 0; c < NC; c++) {
            mbar_wait(sb + 16 * ps + 8, pph);
            const int s = ps;
            if (++ps == 3) { ps = 0; pph ^= 1u; }
            const uint32_t stg = stg0 + (uint32_t)s * 32768u;
            const __half* ws = g_wt0 + (size_t)c * 16384 + (size_t)hseg * 64;
#pragma unroll
            for (int i = 0; i < 16; i++) {
                const int p = ptid + i * 64, h = p >> 3, j = p & 7;
                cp16(stg + 16384u + (uint32_t)h * 128u + (uint32_t)((j ^ (h & 7)) << 4),
                     ws + (size_t)h * 64 + j * 8);
            }
            cp_mbar_arrive(sb + 16 * s);
            int m0 = 0;
            while (tribase(m0 + 1) <= 64 * c) ++m0;
            const int n0 = m0 + (64 * c - tribase(m0));
#pragma unroll
            for (int r2 = 0; r2 < 2; r2++) {
                const int row = ptid + r2 * 64;
                const float* xr = r2 ? xr1 : xr0;
                const uint32_t asw = (uint32_t)(row & 7);
                char* ab = smb + (stg - sb) + (uint32_t)row * 128u;
                int m = m0, n = n0;
#pragma unroll
                for (int j = 0; j < 8; j++) {
                    float f[8];
#pragma unroll
                    for (int q = 0; q < 8; q++) {
                        if (64 * c + 8 * j + q < 528) {
                            f[q] = xr[m] * xr[n];
                            if (++n == 32) { ++m; n = m; }
                        } else f[q] = 0.0f;
                    }
                    uint4 v;
                    v.x = h2u(__floats2half2_rn(f[0], f[1]));
                    v.y = h2u(__floats2half2_rn(f[2], f[3]));
                    v.z = h2u(__floats2half2_rn(f[4], f[5]));
                    v.w = h2u(__floats2half2_rn(f[6], f[7]));
                    *reinterpret_cast<uint4*>(ab + ((((uint32_t)j) ^ asw) << 4)) = v;
                }
            }
            mbar_arrive(sb + 16 * s);
        }
        return;
    }

    const int mg = wid >> 1, ng = wid & 1;
    const int arow = mg * 64 + (lane & 15);
    const int brow = ng * 64 + ((lane >> 4) << 3) + (lane & 7);
    const uint32_t axor = (uint32_t)(arow & 7), bxor = (uint32_t)(brow & 7);
    const uint32_t aof = (uint32_t)arow * 128u, bof = 16384u + (uint32_t)brow * 128u;
    const uint32_t acs = (uint32_t)(lane >> 4), bcs = (uint32_t)((lane >> 3) & 1);

    float acc[4][8][4];
#pragma unroll
    for (int i = 0; i < 4; i++)
#pragma unroll
        for (int j = 0; j < 8; j++)
#pragma unroll
            for (int q = 0; q < 4; q++) acc[i][j][q] = 0.0f;

    int cs = 0; uint32_t cph = 0;
    for (int c = 0; c < NC; c++) {
        mbar_wait(sb + 16 * cs, cph);
        const int s = cs;
        if (++cs == 3) { cs = 0; cph ^= 1u; }
        const uint32_t stg = stg0 + (uint32_t)s * 32768u;
#pragma unroll
        for (int ks = 0; ks < 4; ks++) {
            uint32_t af[4][4], bf[4][4];
#pragma unroll
            for (int mt = 0; mt < 4; mt++)
                ldsm4(af[mt], stg + aof + (uint32_t)(mt * 16 * 128) +
                              ((((uint32_t)(2 * ks) + acs) ^ axor) << 4));
#pragma unroll
            for (int np = 0; np < 4; np++)
                ldsm4(bf[np], stg + bof + (uint32_t)(np * 16 * 128) +
                              ((((uint32_t)(2 * ks) + bcs) ^ bxor) << 4));
#pragma unroll
            for (int mt = 0; mt < 4; mt++)
#pragma unroll
                for (int nt = 0; nt < 8; nt++)
                    mma16(acc[mt][nt], af[mt], &bf[nt >> 1][(nt & 1) * 2]);
        }
        mbar_arrive(sb + 16 * s + 8);
    }

    const int b = b0 + mg, dq = lane >> 2, hq = (lane & 3) * 2;
    if (hseg == 0) {
        float p = 0.0f;
#pragma unroll
        for (int nt = 0; nt < 8; nt++) {
            const int hl = ng * 64 + nt * 8 + hq;
            const float bv0 = __ldg(bias + hl), bv1 = __ldg(bias + hl + 1);
            const float w0 = __ldg(fcW + hl), w1 = __ldg(fcW + hl + 1);
            float s0 = 0.0f, s1 = 0.0f;
#pragma unroll
            for (int mt = 0; mt < 4; mt++) {
                s0 += fmaxf(acc[mt][nt][0] + bv0, 0.f) + fmaxf(acc[mt][nt][2] + bv0, 0.f);
                s1 += fmaxf(acc[mt][nt][1] + bv1, 0.f) + fmaxf(acc[mt][nt][3] + bv1, 0.f);
            }
            p += s0 * w0 + s1 * w1;
        }
#pragma unroll
        for (int o = 16; o > 0; o >>= 1) p += __shfl_xor_sync(0xFFFFFFFFu, p, o);
        if (lane == 0) atomicAdd(out + b, p);
    } else {
        float* yo = g_h0 + (size_t)b * 8192;
#pragma unroll
        for (int mt = 0; mt < 4; mt++) {
            const int d = mt * 16 + dq;
#pragma unroll
            for (int nt = 0; nt < 8; nt++) {
                const int hl = ng * 64 + nt * 8 + hq;
                const float bv0 = __ldg(bias + 128 + hl), bv1 = __ldg(bias + 128 + hl + 1);
                yo[(size_t)hl * 64 + d]           = fmaxf(acc[mt][nt][0] + bv0, 0.f);
                yo[(size_t)(hl + 1) * 64 + d]     = fmaxf(acc[mt][nt][1] + bv1, 0.f);
                yo[(size_t)hl * 64 + d + 8]       = fmaxf(acc[mt][nt][2] + bv0, 0.f);
                yo[(size_t)(hl + 1) * 64 + d + 8] = fmaxf(acc[mt][nt][3] + bv1, 0.f);
            }
        }
    }
}

// ---------------- L1/L2: A-in-registers fp16 mma.sync ----------------
// Grid 2048 = 512 batch-pairs x 4 h-segments of 64. 128 threads = 4 warps:
// warp (bb = wid>>1, hh = wid&1) covers batch b0+bb, h rows hseg+hh*32..+32, all 64 d.
// A-frag = hmul2(x-splat, h-pair): no A SMEM traffic. B: 3-stage cp.async (8KB).
// hcache hc[bb][c][d] = half2(h[2c][d], h[2c+1][d]) (32KB). occ 2.
template <int L>
__global__ void __launch_bounds__(128, 2)
cin_big(const float* __restrict__ x, const float* __restrict__ bias,
        const float* __restrict__ fcW, float* __restrict__ out) {
    const __half* wt  = (L == 1) ? g_wt1 : g_wt2;
    const float* hsrc = (L == 1) ? g_h0 : g_h1;

    extern __shared__ char smc[];
    const uint32_t sb = (smem_u32(smc) + 1023u) & ~1023u;
    const uint32_t stg0 = sb;            // 3 x 8KB B stages
    const uint32_t hc   = sb + 24576u;   // 32KB hcache

    const int t = threadIdx.x, lane = t & 31, wid = t >> 5;
    const int b0 = (blockIdx.x >> 2) * 2, hseg = (blockIdx.x & 3) * 64;
    const int bb = wid >> 1, hh = wid & 1;
    const int g = lane >> 2, tid4 = lane & 3;

    auto cpB = [&](int c) {
        const __half* ws = wt + (size_t)c * 16384 + (size_t)hseg * 64;
        const uint32_t stg = stg0 + (uint32_t)(c % 3) * 8192u;
#pragma unroll
        for (int i = 0; i < 4; i++) {
            const int q = t + i * 128, row = q >> 3, j = q & 7;
            cp16(stg + (uint32_t)row * 128u + (uint32_t)((j ^ (row & 7)) << 4),
                 ws + (size_t)row * 64 + j * 8);
        }
        cp_commit();
    };
    cpB(0); cpB(1);

    {   // hcache build
        const float* h0 = hsrc + (size_t)b0 * 8192;
#pragma unroll 4
        for (int i = 0; i < 64; i++) {
            const int idx = t + i * 128;
            const int b2 = idx >> 12, loc = idx & 4095, c = loc >> 6, d = loc & 63;
            const float v0 = h0[(size_t)b2 * 8192 + (size_t)(2 * c) * 64 + d];
            const float v1 = h0[(size_t)b2 * 8192 + (size_t)(2 * c + 1) * 64 + d];
            const uint32_t pv = h2u(__floats2half2_rn(v0, v1));
            asm volatile("st.shared.b32 [%0], %1;" :: "r"(hc + (uint32_t)idx * 4u), "r"(pv) : "memory");
        }
    }

    // x splats: xs[s*8 + dd], m = tid4+4s, d = (dd>>1)*16 + (dd&1)*8 + g
    uint32_t xs[64];
    {
        const float* xp = x + (size_t)(b0 + bb) * 2048;
#pragma unroll
        for (int s = 0; s < 8; s++)
#pragma unroll
            for (int dd = 0; dd < 8; dd++) {
                const float v = __ldg(xp + (tid4 + 4 * s) * 64 + (dd >> 1) * 16 + (dd & 1) * 8 + g);
                xs[s * 8 + dd] = h2u(__floats2half2_rn(v, v));
            }
    }

    const int brow = hh * 32 + ((lane >> 4) << 3) + (lane & 7);
    const uint32_t bxor = (uint32_t)(brow & 7), bof = (uint32_t)brow * 128u;
    const uint32_t bcs = (uint32_t)((lane >> 3) & 1);
    const uint32_t hcb = hc + (uint32_t)bb * 16384u;

    float acc[4][4][4];
#pragma unroll
    for (int i = 0; i < 4; i++)
#pragma unroll
        for (int j = 0; j < 4; j++)
#pragma unroll
            for (int q = 0; q < 4; q++) acc[i][j][q] = 0.0f;

    for (int c = 0; c < 64; c++) {
        if (c + 2 < 64) cp_wait<1>(); else cp_wait<0>();
        __syncthreads();
        if (c + 2 < 64) cpB(c + 2);

        uint32_t hp[8];
#pragma unroll
        for (int dd = 0; dd < 8; dd++) {
            const int d = (dd >> 1) * 16 + (dd & 1) * 8 + g;
            asm volatile("ld.shared.b32 %0, [%1];"
                         : "=r"(hp[dd]) : "r"(hcb + (uint32_t)(c * 256 + d * 4)));
        }
        const uint32_t stg = stg0 + (uint32_t)(c % 3) * 8192u;
#pragma unroll
        for (int ks = 0; ks < 4; ks++) {
            uint32_t bf[2][4];
#pragma unroll
            for (int np = 0; np < 2; np++)
                ldsm4(bf[np], stg + bof + (uint32_t)(np * 16 * 128) +
                              ((((uint32_t)(2 * ks) + bcs) ^ bxor) << 4));
            uint32_t af[4][4];
#pragma unroll
            for (int mt = 0; mt < 4; mt++) {
                af[mt][0] = hmul2(xs[(2 * ks) * 8 + 2 * mt],         hp[2 * mt]);
                af[mt][1] = hmul2(xs[(2 * ks) * 8 + 2 * mt + 1],     hp[2 * mt + 1]);
                af[mt][2] = hmul2(xs[(2 * ks + 1) * 8 + 2 * mt],     hp[2 * mt]);
                af[mt][3] = hmul2(xs[(2 * ks + 1) * 8 + 2 * mt + 1], hp[2 * mt + 1]);
            }
#pragma unroll
            for (int mt = 0; mt < 4; mt++)
#pragma unroll
                for (int nt = 0; nt < 4; nt++)
                    mma16(acc[mt][nt], af[mt], &bf[nt >> 1][(nt & 1) * 2]);
        }
    }

    const int b = b0 + bb, hq = tid4 * 2, dq = g;
    const int hbase = hseg + hh * 32;
    if (L == 2 || hseg < 128) {
        const int fcoff = ((L == 1) ? 128 : 256) + hbase;
        float p = 0.0f;
#pragma unroll
        for (int nt = 0; nt < 4; nt++) {
            const int hl = nt * 8 + hq;
            const float bv0 = __ldg(bias + hbase + hl), bv1 = __ldg(bias + hbase + hl + 1);
            const float w0 = __ldg(fcW + fcoff + hl), w1 = __ldg(fcW + fcoff + hl + 1);
            float s0 = 0.0f, s1 = 0.0f;
#pragma unroll
            for (int mt = 0; mt < 4; mt++) {
                s0 += fmaxf(acc[mt][nt][0] + bv0, 0.f) + fmaxf(acc[mt][nt][2] + bv0, 0.f);
                s1 += fmaxf(acc[mt][nt][1] + bv1, 0.f) + fmaxf(acc[mt][nt][3] + bv1, 0.f);
            }
            p += s0 * w0 + s1 * w1;
        }
#pragma unroll
        for (int o = 16; o > 0; o >>= 1) p += __shfl_xor_sync(0xFFFFFFFFu, p, o);
        if (lane == 0) atomicAdd(out + b, p);
    } else {
        float* yo = g_h1 + (size_t)b * 8192;
        const int nb = hbase - 128;
#pragma unroll
        for (int mt = 0; mt < 4; mt++) {
            const int d = mt * 16 + dq;
#pragma unroll
            for (int nt = 0; nt < 4; nt++) {
                const int n = nb + nt * 8 + hq;
                const float bv0 = __ldg(bias + 128 + n), bv1 = __ldg(bias + 128 + n + 1);
                yo[(size_t)n * 64 + d]           = fmaxf(acc[mt][nt][0] + bv0, 0.f);
                yo[(size_t)(n + 1) * 64 + d]     = fmaxf(acc[mt][nt][1] + bv1, 0.f);
                yo[(size_t)n * 64 + d + 8]       = fmaxf(acc[mt][nt][2] + bv0, 0.f);
                yo[(size_t)(n + 1) * 64 + d + 8] = fmaxf(acc[mt][nt][3] + bv1, 0.f);
            }
        }
    }
}

extern "C" void kernel_launch(void* const* d_in, const int* in_sizes, int n_in,
                              void* d_out, int out_size) {
    const float* x   = (const float*)d_in[0];
    const float* W0  = (const float*)d_in[1];
    const float* b0  = (const float*)d_in[2];
    const float* W1  = (const float*)d_in[3];
    const float* b1  = (const float*)d_in[4];
    const float* W2  = (const float*)d_in[5];
    const float* b2  = (const float*)d_in[6];
    const float* fcW = (const float*)d_in[7];
    const float* fcb = (const float*)d_in[8];
    float* out = (float*)d_out;

    constexpr int SM0 = 1024 + 1024 + 3 * 32768;       // cin_l0
    constexpr int SMB = 1024 + 3 * 8192 + 32768;       // cin_big
    cudaFuncSetAttribute(cin_l0, cudaFuncAttributeMaxDynamicSharedMemorySize, SM0);
    cudaFuncSetAttribute(cin_big<1>, cudaFuncAttributeMaxDynamicSharedMemorySize, SMB);
    cudaFuncSetAttribute(cin_big<2>, cudaFuncAttributeMaxDynamicSharedMemorySize, SMB);

    __half *wt0p, *wt1p, *wt2p;
    cudaGetSymbolAddress((void**)&wt0p, g_wt0);
    cudaGetSymbolAddress((void**)&wt1p, g_wt1);
    cudaGetSymbolAddress((void**)&wt2p, g_wt2);

    prep<<<141, 256>>>(W0, W1, W2, fcb, out, wt0p, wt1p, wt2p);

    cin_l0    <<<1024, 192, SM0>>>(x, b0, fcW, out);
    cin_big<1><<<2048, 128, SMB>>>(x, b1, fcW, out);
    cin_big<2><<<2048, 128, SMB>>>(x, b2, fcW, out);
}

// round 14
// speedup vs baseline: 1.1068x; 1.1068x over previous
#include <cuda_runtime.h>
#include <cuda_fp16.h>
#include <cstdint>

// h of layers 0/1 (rows>=128) as f16x2 pairs: g_h2*[b][c][d] = (h[2c,d], h[2c+1,d]).
__device__ uint32_t g_h2a[1024 * 4096];
__device__ uint32_t g_h2b[1024 * 4096];
__device__ __half g_wt0[9 * 16384];     // L0 folded (R11 mapping)
__device__ __half g_wt1[256 * 4096];    // L1/L2: Wt[c][h][kk], kk = 2m+nl, n = 2c+nl
__device__ __half g_wt2[256 * 4096];

__device__ __forceinline__ uint32_t smem_u32(const void* p) {
    uint32_t r;
    asm("{ .reg .u64 t; cvta.to.shared.u64 t, %1; cvt.u32.u64 %0, t; }" : "=r"(r) : "l"(p));
    return r;
}
__device__ __forceinline__ uint32_t h2u(__half2 v) { return *reinterpret_cast<uint32_t*>(&v); }
__device__ __forceinline__ uint32_t hmul2(uint32_t a, uint32_t b) {
    uint32_t r;
    asm("mul.rn.f16x2 %0, %1, %2;" : "=r"(r) : "r"(a), "r"(b));
    return r;
}
__device__ __forceinline__ void cp16(uint32_t dst, const void* src) {
    asm volatile("cp.async.cg.shared.global [%0], [%1], 16;" :: "r"(dst), "l"(src) : "memory");
}
__device__ __forceinline__ void cp_commit() { asm volatile("cp.async.commit_group;" ::: "memory"); }
template <int N>
__device__ __forceinline__ void cp_wait() { asm volatile("cp.async.wait_group %0;" :: "n"(N) : "memory"); }
__device__ __forceinline__ void cp_mbar_arrive(uint32_t mbar) {
    asm volatile("cp.async.mbarrier.arrive.noinc.shared.b64 [%0];" :: "r"(mbar) : "memory");
}
__device__ __forceinline__ void mbar_init(uint32_t a, uint32_t c) {
    asm volatile("mbarrier.init.shared.b64 [%0], %1;" :: "r"(a), "r"(c) : "memory");
}
__device__ __forceinline__ void mbar_arrive(uint32_t a) {
    asm volatile("mbarrier.arrive.shared.b64 _, [%0];" :: "r"(a) : "memory");
}
__device__ __forceinline__ void mbar_wait(uint32_t a, uint32_t ph) {
    asm volatile(
        "{\n\t.reg .pred P;\n"
        "W_%=:\n\tmbarrier.try_wait.parity.shared.b64 P, [%0], %1, 0x989680;\n\t"
        "@P bra.uni D_%=;\n\tbra.uni W_%=;\nD_%=:\n\t}"
        :: "r"(a), "r"(ph) : "memory");
}
__device__ __forceinline__ void ldsm4(uint32_t* r, uint32_t a) {
    asm volatile("ldmatrix.sync.aligned.m8n8.x4.shared.b16 {%0,%1,%2,%3}, [%4];"
                 : "=r"(r[0]), "=r"(r[1]), "=r"(r[2]), "=r"(r[3]) : "r"(a));
}
__device__ __forceinline__ void mma16(float* c, const uint32_t* a, const uint32_t* b) {
    asm volatile("mma.sync.aligned.m16n8k16.row.col.f32.f16.f16.f32 "
                 "{%0,%1,%2,%3},{%4,%5,%6,%7},{%8,%9},{%0,%1,%2,%3};"
                 : "+f"(c[0]), "+f"(c[1]), "+f"(c[2]), "+f"(c[3])
                 : "r"(a[0]), "r"(a[1]), "r"(a[2]), "r"(a[3]), "r"(b[0]), "r"(b[1]));
}
__device__ __forceinline__ int tribase(int m) { return 32 * m - ((m * (m - 1)) >> 1); }

// ---------------- prep: weight transposes + out init ----------------
__global__ void __launch_bounds__(256)
prep(const float* __restrict__ W0, const float* __restrict__ W1, const float* __restrict__ W2,
     const float* __restrict__ fcb, float* __restrict__ out,
     __half* __restrict__ wt0, __half* __restrict__ wt1, __half* __restrict__ wt2) {
    const int bx = blockIdx.x, t = threadIdx.x;
    if (bx >= 137) { out[(bx - 137) * 256 + t] = fcb[0]; return; }
    __shared__ __half s[64 * 256];
    __half* dst;
    if (bx < 9) {
        const int c = bx, p0 = 64 * c;
        int m = 0;
        while (tribase(m + 1) <= p0) ++m;
        int n = m + (p0 - tribase(m));
        for (int kk = 0; kk < 64; kk++) {
            float v = 0.0f;
            if (p0 + kk < 528) {
                v = W0[(size_t)(m * 32 + n) * 256 + t];
                if (n > m) v += W0[(size_t)(n * 32 + m) * 256 + t];
                if (++n == 32) { ++m; n = m; }
            }
            s[kk * 256 + t] = __float2half_rn(v);
        }
        dst = wt0 + (size_t)c * 16384 + (size_t)t * 64;
    } else {
        const int c = (bx < 73) ? (bx - 9) : (bx - 73);
        const float* W = (bx < 73) ? W1 : W2;
#pragma unroll 4
        for (int kk = 0; kk < 64; kk++) {
            const int m = kk >> 1, nl = kk & 1;
            const int k = m * 128 + 2 * c + nl;
            s[kk * 256 + t] = __float2half_rn(W[(size_t)k * 256 + t]);
        }
        dst = ((bx < 73) ? wt1 : wt2) + (size_t)c * 16384 + (size_t)t * 64;
    }
    __syncthreads();
#pragma unroll
    for (int j = 0; j < 8; j++) {
        uint4 v;
        v.x = h2u(__halves2half2(s[(8 * j + 0) * 256 + t], s[(8 * j + 1) * 256 + t]));
        v.y = h2u(__halves2half2(s[(8 * j + 2) * 256 + t], s[(8 * j + 3) * 256 + t]));
        v.z = h2u(__halves2half2(s[(8 * j + 4) * 256 + t], s[(8 * j + 5) * 256 + t]));
        v.w = h2u(__halves2half2(s[(8 * j + 6) * 256 + t], s[(8 * j + 7) * 256 + t]));
        *reinterpret_cast<uint4*>(dst + 8 * j) = v;
    }
}

// ---------------- L0: proven warp-specialized folded kernel; h2a output ----------------
__global__ void __launch_bounds__(192, 2)
cin_l0(const float* __restrict__ x, const float* __restrict__ bias,
       const float* __restrict__ fcW, float* __restrict__ out) {
    constexpr int NC = 9;
    extern __shared__ char smc[];
    const uint32_t sb0 = smem_u32(smc);
    const uint32_t sb  = (sb0 + 1023u) & ~1023u;
    char* const smb    = smc + (sb - sb0);
    const uint32_t stg0 = sb + 1024u;
    const int t = threadIdx.x, lane = t & 31, wid = t >> 5;
    const int b0 = (blockIdx.x >> 1) * 2, hseg = (blockIdx.x & 1) * 128;

    if (t == 0) {
#pragma unroll
        for (int s = 0; s < 3; s++) { mbar_init(sb + 16 * s, 128); mbar_init(sb + 16 * s + 8, 128); }
    }
    __syncthreads();

    if (t >= 128) {
        const int ptid = t - 128;
        float xr0[32], xr1[32];
        {
            const float* xp0 = x + (size_t)b0 * 2048 + ptid;
            const float* xp1 = x + (size_t)(b0 + 1) * 2048 + ptid;
#pragma unroll
            for (int m = 0; m < 32; m++) { xr0[m] = xp0[m * 64]; xr1[m] = xp1[m * 64]; }
        }
        int ps = 0; uint32_t pph = 1;
        for (int c = 0; c < NC; c++) {
            mbar_wait(sb + 16 * ps + 8, pph);
            const int s = ps;
            if (++ps == 3) { ps = 0; pph ^= 1u; }
            const uint32_t stg = stg0 + (uint32_t)s * 32768u;
            const __half* ws = g_wt0 + (size_t)c * 16384 + (size_t)hseg * 64;
#pragma unroll
            for (int i = 0; i < 16; i++) {
                const int p = ptid + i * 64, h = p >> 3, j = p & 7;
                cp16(stg + 16384u + (uint32_t)h * 128u + (uint32_t)((j ^ (h & 7)) << 4),
                     ws + (size_t)h * 64 + j * 8);
            }
            cp_mbar_arrive(sb + 16 * s);
            int m0 = 0;
            while (tribase(m0 + 1) <= 64 * c) ++m0;
            const int n0 = m0 + (64 * c - tribase(m0));
#pragma unroll
            for (int r2 = 0; r2 < 2; r2++) {
                const int row = ptid + r2 * 64;
                const float* xr = r2 ? xr1 : xr0;
                const uint32_t asw = (uint32_t)(row & 7);
                char* ab = smb + (stg - sb) + (uint32_t)row * 128u;
                int m = m0, n = n0;
#pragma unroll
                for (int j = 0; j < 8; j++) {
                    float f[8];
#pragma unroll
                    for (int q = 0; q < 8; q++) {
                        if (64 * c + 8 * j + q < 528) {
                            f[q] = xr[m] * xr[n];
                            if (++n == 32) { ++m; n = m; }
                        } else f[q] = 0.0f;
                    }
                    uint4 v;
                    v.x = h2u(__floats2half2_rn(f[0], f[1]));
                    v.y = h2u(__floats2half2_rn(f[2], f[3]));
                    v.z = h2u(__floats2half2_rn(f[4], f[5]));
                    v.w = h2u(__floats2half2_rn(f[6], f[7]));
                    *reinterpret_cast<uint4*>(ab + ((((uint32_t)j) ^ asw) << 4)) = v;
                }
            }
            mbar_arrive(sb + 16 * s);
        }
        return;
    }

    const int mg = wid >> 1, ng = wid & 1;
    const int arow = mg * 64 + (lane & 15);
    const int brow = ng * 64 + ((lane >> 4) << 3) + (lane & 7);
    const uint32_t axor = (uint32_t)(arow & 7), bxor = (uint32_t)(brow & 7);
    const uint32_t aof = (uint32_t)arow * 128u, bof = 16384u + (uint32_t)brow * 128u;
    const uint32_t acs = (uint32_t)(lane >> 4), bcs = (uint32_t)((lane >> 3) & 1);

    float acc[4][8][4];
#pragma unroll
    for (int i = 0; i < 4; i++)
#pragma unroll
        for (int j = 0; j < 8; j++)
#pragma unroll
            for (int q = 0; q < 4; q++) acc[i][j][q] = 0.0f;

    int cs = 0; uint32_t cph = 0;
    for (int c = 0; c < NC; c++) {
        mbar_wait(sb + 16 * cs, cph);
        const int s = cs;
        if (++cs == 3) { cs = 0; cph ^= 1u; }
        const uint32_t stg = stg0 + (uint32_t)s * 32768u;
#pragma unroll
        for (int ks = 0; ks < 4; ks++) {
            uint32_t af[4][4], bf[4][4];
#pragma unroll
            for (int mt = 0; mt < 4; mt++)
                ldsm4(af[mt], stg + aof + (uint32_t)(mt * 16 * 128) +
                              ((((uint32_t)(2 * ks) + acs) ^ axor) << 4));
#pragma unroll
            for (int np = 0; np < 4; np++)
                ldsm4(bf[np], stg + bof + (uint32_t)(np * 16 * 128) +
                              ((((uint32_t)(2 * ks) + bcs) ^ bxor) << 4));
#pragma unroll
            for (int mt = 0; mt < 4; mt++)
#pragma unroll
                for (int nt = 0; nt < 8; nt++)
                    mma16(acc[mt][nt], af[mt], &bf[nt >> 1][(nt & 1) * 2]);
        }
        mbar_arrive(sb + 16 * s + 8);
    }

    const int b = b0 + mg, dq = lane >> 2, hq = (lane & 3) * 2;
    if (hseg == 0) {
        float p = 0.0f;
#pragma unroll
        for (int nt = 0; nt < 8; nt++) {
            const int hl = ng * 64 + nt * 8 + hq;
            const float bv0 = __ldg(bias + hl), bv1 = __ldg(bias + hl + 1);
            const float w0 = __ldg(fcW + hl), w1 = __ldg(fcW + hl + 1);
            float s0 = 0.0f, s1 = 0.0f;
#pragma unroll
            for (int mt = 0; mt < 4; mt++) {
                s0 += fmaxf(acc[mt][nt][0] + bv0, 0.f) + fmaxf(acc[mt][nt][2] + bv0, 0.f);
                s1 += fmaxf(acc[mt][nt][1] + bv1, 0.f) + fmaxf(acc[mt][nt][3] + bv1, 0.f);
            }
            p += s0 * w0 + s1 * w1;
        }
#pragma unroll
        for (int o = 16; o > 0; o >>= 1) p += __shfl_xor_sync(0xFFFFFFFFu, p, o);
        if (lane == 0) atomicAdd(out + b, p);
    } else {
        uint32_t* yo = g_h2a + (size_t)b * 4096;
#pragma unroll
        for (int mt = 0; mt < 4; mt++) {
            const int d = mt * 16 + dq;
#pragma unroll
            for (int nt = 0; nt < 8; nt++) {
                const int hl = ng * 64 + nt * 8 + hq;     // even
                const int c2 = hl >> 1;
                const float bv0 = __ldg(bias + 128 + hl), bv1 = __ldg(bias + 128 + hl + 1);
                yo[c2 * 64 + d] =
                    h2u(__floats2half2_rn(fmaxf(acc[mt][nt][0] + bv0, 0.f),
                                          fmaxf(acc[mt][nt][1] + bv1, 0.f)));
                yo[c2 * 64 + d + 8] =
                    h2u(__floats2half2_rn(fmaxf(acc[mt][nt][2] + bv0, 0.f),
                                          fmaxf(acc[mt][nt][3] + bv1, 0.f)));
            }
        }
    }
}

// ---------------- L1/L2: A-in-regs, warp tile 64x64, 2-warp CTAs ----------------
// Grid 2048 = 512 batch-pairs x 4 h-segments of 64. 64 threads = 2 warps (warp bb = batch).
// Per ks: 16 hmul2 + 4 ldsm + 32 mma. B: 3-stage cp.async (8KB). hcache: raw cp.async
// of f16x2 pairs (32KB, [bb][c][d], d-minor -> conflict-free broadcast LDS). occ 3.
template <int L>
__global__ void __launch_bounds__(64, 3)
cin_big(const float* __restrict__ x, const float* __restrict__ bias,
        const float* __restrict__ fcW, float* __restrict__ out) {
    const __half* wt      = (L == 1) ? g_wt1 : g_wt2;
    const uint32_t* hsrc  = (L == 1) ? g_h2a : g_h2b;

    extern __shared__ char smc[];
    const uint32_t sb = (smem_u32(smc) + 1023u) & ~1023u;
    const uint32_t hc = sb + 24576u;

    const int t = threadIdx.x, lane = t & 31, bb = t >> 5;
    const int b0 = (blockIdx.x >> 2) * 2, hseg = (blockIdx.x & 3) * 64;
    const int g = lane >> 2, tid4 = lane & 3;

    auto cpB = [&](int c) {
        const __half* ws = wt + (size_t)c * 16384 + (size_t)hseg * 64;
        const uint32_t stg = sb + (uint32_t)(c % 3) * 8192u;
#pragma unroll
        for (int i = 0; i < 8; i++) {
            const int q = t + i * 64, row = q >> 3, j = q & 7;
            cp16(stg + (uint32_t)row * 128u + (uint32_t)((j ^ (row & 7)) << 4),
                 ws + (size_t)row * 64 + j * 8);
        }
    };

    {   // prologue: group0 = hcache + B0; group1 = B1
        const char* hs = (const char*)(hsrc + (size_t)b0 * 4096);
#pragma unroll
        for (int i = 0; i < 32; i++) cp16(hc + (uint32_t)(t + i * 64) * 16u, hs + (t + i * 64) * 16);
        cpB(0); cp_commit();
        cpB(1); cp_commit();
    }

    // x splats: xs[j][dd], m = tid4 + 4j, d = (dd>>1)*16 + (dd&1)*8 + g
    uint32_t xs[8][8];
    {
        const float* xp = x + (size_t)(b0 + bb) * 2048;
#pragma unroll
        for (int j = 0; j < 8; j++)
#pragma unroll
            for (int dd = 0; dd < 8; dd++) {
                const float v = __ldg(xp + (tid4 + 4 * j) * 64 + (dd >> 1) * 16 + (dd & 1) * 8 + g);
                xs[j][dd] = h2u(__floats2half2_rn(v, v));
            }
    }

    const int brow = ((lane >> 4) << 3) + (lane & 7);     // + 16*np
    const uint32_t bxor = (uint32_t)(brow & 7), bof = (uint32_t)brow * 128u;
    const uint32_t bcs = (uint32_t)((lane >> 3) & 1);
    const uint32_t hcb = hc + (uint32_t)bb * 16384u;

    float acc[4][8][4];
#pragma unroll
    for (int i = 0; i < 4; i++)
#pragma unroll
        for (int j = 0; j < 8; j++)
#pragma unroll
            for (int q = 0; q < 4; q++) acc[i][j][q] = 0.0f;

    for (int c = 0; c < 64; c++) {
        if (c + 2 < 64) cp_wait<1>(); else cp_wait<0>();
        __syncthreads();
        if (c + 2 < 64) { cpB(c + 2); cp_commit(); }

        uint32_t hp[8];
#pragma unroll
        for (int dd = 0; dd < 8; dd++) {
            const int d = (dd >> 1) * 16 + (dd & 1) * 8 + g;
            asm volatile("ld.shared.b32 %0, [%1];"
                         : "=r"(hp[dd]) : "r"(hcb + (uint32_t)(c * 256 + d * 4)));
        }
        const uint32_t stg = sb + (uint32_t)(c % 3) * 8192u;
#pragma unroll
        for (int ks = 0; ks < 4; ks++) {
            uint32_t bf[4][4];
#pragma unroll
            for (int np = 0; np < 4; np++)
                ldsm4(bf[np], stg + bof + (uint32_t)(np * 16 * 128) +
                              ((((uint32_t)(2 * ks) + bcs) ^ bxor) << 4));
#pragma unroll
            for (int mt = 0; mt < 4; mt++) {
                uint32_t af[4];
                af[0] = hmul2(xs[2 * ks][2 * mt],         hp[2 * mt]);
                af[1] = hmul2(xs[2 * ks][2 * mt + 1],     hp[2 * mt + 1]);
                af[2] = hmul2(xs[2 * ks + 1][2 * mt],     hp[2 * mt]);
                af[3] = hmul2(xs[2 * ks + 1][2 * mt + 1], hp[2 * mt + 1]);
#pragma unroll
                for (int nt = 0; nt < 8; nt++)
                    mma16(acc[mt][nt], af, &bf[nt >> 1][(nt & 1) * 2]);
            }
        }
    }

    const int b = b0 + bb, hq = tid4 * 2;
    if (L == 2 || hseg < 128) {
        const int fcoff = ((L == 1) ? 128 : 256) + hseg;
        float p = 0.0f;
#pragma unroll
        for (int nt = 0; nt < 8; nt++) {
            const int hl = nt * 8 + hq;
            const float bv0 = __ldg(bias + hseg + hl), bv1 = __ldg(bias + hseg + hl + 1);
            const float w0 = __ldg(fcW + fcoff + hl), w1 = __ldg(fcW + fcoff + hl + 1);
            float s0 = 0.0f, s1 = 0.0f;
#pragma unroll
            for (int mt = 0; mt < 4; mt++) {
                s0 += fmaxf(acc[mt][nt][0] + bv0, 0.f) + fmaxf(acc[mt][nt][2] + bv0, 0.f);
                s1 += fmaxf(acc[mt][nt][1] + bv1, 0.f) + fmaxf(acc[mt][nt][3] + bv1, 0.f);
            }
            p += s0 * w0 + s1 * w1;
        }
#pragma unroll
        for (int o = 16; o > 0; o >>= 1) p += __shfl_xor_sync(0xFFFFFFFFu, p, o);
        if (lane == 0) atomicAdd(out + b, p);
    } else {
        uint32_t* yo = g_h2b + (size_t)b * 4096;
        const int nb = hseg - 128;
#pragma unroll
        for (int mt = 0; mt < 4; mt++) {
            const int d = mt * 16 + g;
#pragma unroll
            for (int nt = 0; nt < 8; nt++) {
                const int n = nb + nt * 8 + hq;           // even
                const int c2 = n >> 1;
                const float bv0 = __ldg(bias + 128 + n), bv1 = __ldg(bias + 128 + n + 1);
                yo[c2 * 64 + d] =
                    h2u(__floats2half2_rn(fmaxf(acc[mt][nt][0] + bv0, 0.f),
                                          fmaxf(acc[mt][nt][1] + bv1, 0.f)));
                yo[c2 * 64 + d + 8] =
                    h2u(__floats2half2_rn(fmaxf(acc[mt][nt][2] + bv0, 0.f),
                                          fmaxf(acc[mt][nt][3] + bv1, 0.f)));
            }
        }
    }
}

extern "C" void kernel_launch(void* const* d_in, const int* in_sizes, int n_in,
                              void* d_out, int out_size) {
    const float* x   = (const float*)d_in[0];
    const float* W0  = (const float*)d_in[1];
    const float* b0  = (const float*)d_in[2];
    const float* W1  = (const float*)d_in[3];
    const float* b1  = (const float*)d_in[4];
    const float* W2  = (const float*)d_in[5];
    const float* b2  = (const float*)d_in[6];
    const float* fcW = (const float*)d_in[7];
    const float* fcb = (const float*)d_in[8];
    float* out = (float*)d_out;

    constexpr int SM0 = 1024 + 1024 + 3 * 32768;        // cin_l0
    constexpr int SMB = 1024 + 3 * 8192 + 32768;        // cin_big (58368)
    cudaFuncSetAttribute(cin_l0, cudaFuncAttributeMaxDynamicSharedMemorySize, SM0);
    cudaFuncSetAttribute(cin_big<1>, cudaFuncAttributeMaxDynamicSharedMemorySize, SMB);
    cudaFuncSetAttribute(cin_big<2>, cudaFuncAttributeMaxDynamicSharedMemorySize, SMB);

    __half *wt0p, *wt1p, *wt2p;
    cudaGetSymbolAddress((void**)&wt0p, g_wt0);
    cudaGetSymbolAddress((void**)&wt1p, g_wt1);
    cudaGetSymbolAddress((void**)&wt2p, g_wt2);

    prep<<<141, 256>>>(W0, W1, W2, fcb, out, wt0p, wt1p, wt2p);

    cin_l0    <<<1024, 192, SM0>>>(x, b0, fcW, out);
    cin_big<1><<<2048,  64, SMB>>>(x, b1, fcW, out);
    cin_big<2><<<2048,  64, SMB>>>(x, b2, fcW, out);
}